// round 5
// baseline (speedup 1.0000x reference)
#include <cuda_runtime.h>
#include <cuda_bf16.h>
#include <math.h>

// Attention path collapses (softmax rows sum to 1; T,S fully contracted):
//   y = 1024 * (h_pred @ Wv + bv)
// Only Wv/Wo projection + gate MLP + mixer MLP survive.
//
// R4: R3 dataflow (merged phases, 9 barriers, hoisted biases) with all smem
// traffic as plain C++ ulonglong2 accesses (LDS.128/STS.128, correctly
// ordered by barriers — R3's non-volatile asm loads were reordered across
// __syncthreads by the compiler, causing rel_err 0.44).

#define HID 128
#define ROWS 8
#define SLICES 8
#define KS (HID / SLICES)        // 16
#define NNODES 1024
#define NTHREADS (HID * SLICES)  // 1024

typedef unsigned long long u64;

__device__ __forceinline__ u64 fma2(u64 a, u64 b, u64 c) {
    u64 d;
    asm("fma.rn.f32x2 %0, %1, %2, %3;" : "=l"(d) : "l"(a), "l"(b), "l"(c));
    return d;
}

// Partial GEMM over this slice's k-range. Activations in smem, layout
// [k][8 rows] fp32 (two LDS.128 per k); weights preloaded 16-deep from L2.
__device__ __forceinline__ void gemm_slice(const float* __restrict__ W,
                                           const float* __restrict__ act,
                                           int c, int k0, u64 acc[4]) {
    float w[KS];
#pragma unroll
    for (int i = 0; i < KS; i++) w[i] = W[(k0 + i) * HID + c];
#pragma unroll
    for (int i = 0; i < KS; i++) {
        u64 ww;
        asm("mov.b64 %0, {%1, %1};" : "=l"(ww) : "f"(w[i]));
        const ulonglong2* a = (const ulonglong2*)(act + (k0 + i) * ROWS);
        ulonglong2 a01 = a[0];   // rows 0..3
        ulonglong2 a23 = a[1];   // rows 4..7
        acc[0] = fma2(a01.x, ww, acc[0]);
        acc[1] = fma2(a01.y, ww, acc[1]);
        acc[2] = fma2(a23.x, ww, acc[2]);
        acc[3] = fma2(a23.y, ww, acc[3]);
    }
}

__device__ __forceinline__ void part_store(float* dst, const u64 acc[4]) {
    ulonglong2* d = (ulonglong2*)dst;
    d[0] = make_ulonglong2(acc[0], acc[1]);
    d[1] = make_ulonglong2(acc[2], acc[3]);
}

extern "C" __global__ void __launch_bounds__(NTHREADS, 1)
temporal_attn_fused(const float* __restrict__ h_prev,
                    const float* __restrict__ h_pred,
                    const float* __restrict__ Wv, const float* __restrict__ bv,
                    const float* __restrict__ Wo, const float* __restrict__ bo,
                    const float* __restrict__ gW1, const float* __restrict__ gb1,
                    const float* __restrict__ gW2, const float* __restrict__ gb2,
                    const float* __restrict__ mW1, const float* __restrict__ mb1,
                    const float* __restrict__ mW2, const float* __restrict__ mb2,
                    float* __restrict__ out) {
    extern __shared__ float smf[];
    // Floats: [0] bufA = h_pred, later h_corr   [1024] hv = h_prev
    //         [2048] bufC = v, later m1         [3072] g1
    //         [4096] partA (8192)               [12288] partB (8192)
    float* bufA = smf;
    float* hvF  = smf + 1024;
    float* bufC = smf + 2048;
    float* g1F  = smf + 3072;
    float* pA   = smf + 4096;
    float* pB   = smf + 12288;

    const int tid = threadIdx.x;
    const int c = tid & (HID - 1);   // output column (GEMM phase)
    const int s = tid >> 7;          // k-slice 0..7
    const int k0 = s * KS;
    const int r0 = blockIdx.x * ROWS;
    const int p = tid;               // element owned in reduce phases
    const int q = p >> 3;            // its column index

    // Hoisted bias loads (off the post-barrier critical paths).
    const float bv_r  = bv[q],  bo_r  = bo[q];
    const float gb1_r = gb1[q], gb2_r = gb2[q];
    const float mb1_r = mb1[q], mb2_r = mb2[q];

    // Stage input tiles transposed: [k][r], coalesced global reads.
    {
        int r = tid >> 7, cc = tid & (HID - 1);
        bufA[cc * ROWS + r] = h_pred[(r0 + r) * HID + cc];
        hvF[cc * ROWS + r]  = h_prev[(r0 + r) * HID + cc];
    }
    __syncthreads();

    u64 acc[4];
    float* pAdst = pA + s * 1024 + c * ROWS;
    float* pBdst = pB + s * 1024 + c * ROWS;

#define GEMM_ZERO() { acc[0] = acc[1] = acc[2] = acc[3] = 0ULL; }
#define REDUCE8(x, base) float x = base[p] + base[1024 + p] + base[2048 + p] + base[3072 + p] \
                                 + base[4096 + p] + base[5120 + p] + base[6144 + p] + base[7168 + p]

    float outv, hcv;

    // ======== P1: S1 (v = hp@Wv) -> pA ; S3 (gate-hidden pre-act) -> pB ========
    GEMM_ZERO();
    gemm_slice(Wv, bufA, c, k0, acc);
    part_store(pAdst, acc);
    GEMM_ZERO();
    gemm_slice(gW1, bufA, c, k0, acc);
    gemm_slice(gW1 + HID * HID, hvF, c, k0, acc);
    part_store(pBdst, acc);
    __syncthreads();
    {
        REDUCE8(v, pA);
        bufC[p] = v + bv_r;                        // v
        REDUCE8(x, pB);
        x += gb1_r;
        g1F[p] = x / (1.0f + __expf(-x));          // silu -> g1
    }
    __syncthreads();

    // ======== P2: S2 (v@Wo) -> pA ; S4 (g1@gW2) -> pB ========
    GEMM_ZERO();
    gemm_slice(Wo, bufC, c, k0, acc);
    part_store(pAdst, acc);
    GEMM_ZERO();
    gemm_slice(gW2, g1F, c, k0, acc);
    part_store(pBdst, acc);
    __syncthreads();
    {
        REDUCE8(v, pA);
        outv = (float)NNODES * v + bo_r;
        REDUCE8(x, pB);
        x += gb2_r;
        float g = 1.0f / (1.0f + __expf(-x));
        hcv = hvF[p] + g * outv;
        bufA[p] = hcv;                             // h_corr (h_pred dead)
    }
    __syncthreads();

    // ======== P3: S5 (hc@mW1_top + hv@mW1_bot) -> pA ========
    GEMM_ZERO();
    gemm_slice(mW1, bufA, c, k0, acc);
    gemm_slice(mW1 + HID * HID, hvF, c, k0, acc);
    part_store(pAdst, acc);
    __syncthreads();
    {
        REDUCE8(x, pA);
        bufC[p] = fmaxf(x + mb1_r, 0.0f);          // m1 (v dead)
    }
    __syncthreads();

    // ======== P4: S6 (m1@mW2) ; final write ========
    GEMM_ZERO();
    gemm_slice(mW2, bufC, c, k0, acc);
    part_store(pAdst, acc);
    __syncthreads();
    {
        REDUCE8(v, pA);
        out[(r0 + (p & 7)) * HID + q] = hcv + v + mb2_r;
    }
}

extern "C" void kernel_launch(void* const* d_in, const int* in_sizes, int n_in,
                              void* d_out, int out_size) {
    // metadata order: h_prev, h_pred, adj_rows, adj_cols, Wq, bq, Wk, bk,
    //                 Wv, bv, Wo, bo, gW1, gb1, gW2, gb2, mW1, mb1, mW2, mb2
    const float* h_prev = (const float*)d_in[0];
    const float* h_pred = (const float*)d_in[1];
    // d_in[2..7] (adjacency, Wq/bq/Wk/bk) are algebraically dead.
    const float* Wv  = (const float*)d_in[8];
    const float* bv  = (const float*)d_in[9];
    const float* Wo  = (const float*)d_in[10];
    const float* bo  = (const float*)d_in[11];
    const float* gW1 = (const float*)d_in[12];
    const float* gb1 = (const float*)d_in[13];
    const float* gW2 = (const float*)d_in[14];
    const float* gb2 = (const float*)d_in[15];
    const float* mW1 = (const float*)d_in[16];
    const float* mb1 = (const float*)d_in[17];
    const float* mW2 = (const float*)d_in[18];
    const float* mb2 = (const float*)d_in[19];
    float* out = (float*)d_out;

    const size_t smem = 80 * 1024;
    static int configured = 0;
    if (!configured) {
        cudaFuncSetAttribute(temporal_attn_fused,
                             cudaFuncAttributeMaxDynamicSharedMemorySize, (int)smem);
        configured = 1;
    }
    temporal_attn_fused<<<NNODES / ROWS, NTHREADS, smem>>>(
        h_prev, h_pred, Wv, bv, Wo, bo,
        gW1, gb1, gW2, gb2, mW1, mb1, mW2, mb2, out);
}

// round 6
// speedup vs baseline: 1.0011x; 1.0011x over previous
#include <cuda_runtime.h>
#include <cuda_bf16.h>
#include <math.h>

// Attention path collapses (softmax rows sum to 1; T,S fully contracted):
//   y = 1024 * (h_pred @ Wv + bv)
// Only Wv/Wo projection + gate MLP + mixer MLP survive.
//
// R5: back to <=48KB STATIC smem (no cudaFuncSetAttribute, no carveout opt-in
// — R4's 80KB dynamic smem cost ~10us per graph replay in wall time).
// Keeps LDS.128 activation loads, 16-deep weight preload, hoisted biases,
// register-carried out/h_corr. S2+S4 run merged (balanced 4/4 slice split).

#define HID 128
#define ROWS 8
#define SLICES 8
#define KS (HID / SLICES)        // 16
#define NNODES 1024
#define NTHREADS (HID * SLICES)  // 1024

typedef unsigned long long u64;

__device__ __forceinline__ u64 fma2(u64 a, u64 b, u64 c) {
    u64 d;
    asm("fma.rn.f32x2 %0, %1, %2, %3;" : "=l"(d) : "l"(a), "l"(b), "l"(c));
    return d;
}

// Partial GEMM over [k0, k0+KSZ): activations from smem ([k][8 rows] fp32,
// two LDS.128 per k, warp-broadcast), weights preloaded 16-deep from L2.
template <int KSZ>
__device__ __forceinline__ void gemm_slice(const float* __restrict__ W,
                                           const float* __restrict__ act,
                                           int c, int k0, u64 acc[4]) {
#pragma unroll
    for (int ch = 0; ch < KSZ; ch += 16) {
        float w[16];
#pragma unroll
        for (int i = 0; i < 16; i++) w[i] = W[(k0 + ch + i) * HID + c];
#pragma unroll
        for (int i = 0; i < 16; i++) {
            u64 ww;
            asm("mov.b64 %0, {%1, %1};" : "=l"(ww) : "f"(w[i]));
            const ulonglong2* a = (const ulonglong2*)(act + (k0 + ch + i) * ROWS);
            ulonglong2 a01 = a[0];   // rows 0..3
            ulonglong2 a23 = a[1];   // rows 4..7
            acc[0] = fma2(a01.x, ww, acc[0]);
            acc[1] = fma2(a01.y, ww, acc[1]);
            acc[2] = fma2(a23.x, ww, acc[2]);
            acc[3] = fma2(a23.y, ww, acc[3]);
        }
    }
}

__device__ __forceinline__ void part_store(float* dst, const u64 acc[4]) {
    ulonglong2* d = (ulonglong2*)dst;
    d[0] = make_ulonglong2(acc[0], acc[1]);
    d[1] = make_ulonglong2(acc[2], acc[3]);
}

extern "C" __global__ void __launch_bounds__(NTHREADS, 1)
temporal_attn_fused(const float* __restrict__ h_prev,
                    const float* __restrict__ h_pred,
                    const float* __restrict__ Wv, const float* __restrict__ bv,
                    const float* __restrict__ Wo, const float* __restrict__ bo,
                    const float* __restrict__ gW1, const float* __restrict__ gb1,
                    const float* __restrict__ gW2, const float* __restrict__ gb2,
                    const float* __restrict__ mW1, const float* __restrict__ mb1,
                    const float* __restrict__ mW2, const float* __restrict__ mb2,
                    float* __restrict__ out) {
    // 48KB static total — no carveout opt-in needed.
    __shared__ float bufA[HID * ROWS];   // 4KB  h_pred, later h_corr
    __shared__ float hvF[HID * ROWS];    // 4KB  h_prev
    __shared__ float bufC[HID * ROWS];   // 4KB  v, later m1
    __shared__ float g1F[HID * ROWS];    // 4KB  gate hidden
    __shared__ float pA[SLICES * HID * ROWS];  // 32KB partials

    const int tid = threadIdx.x;
    const int c = tid & (HID - 1);   // output column (GEMM phase)
    const int s = tid >> 7;          // k-slice 0..7
    const int k0 = s * KS;
    const int r0 = blockIdx.x * ROWS;
    const int p = tid;               // element owned in reduce phases
    const int q = p >> 3;            // its column index

    // Hoisted bias loads (off the post-barrier critical paths).
    const float bv_r  = bv[q],  bo_r  = bo[q];
    const float gb1_r = gb1[q], gb2_r = gb2[q];
    const float mb1_r = mb1[q], mb2_r = mb2[q];

    // Stage input tiles transposed: [k][r], coalesced global reads.
    {
        int r = tid >> 7, cc = tid & (HID - 1);
        bufA[cc * ROWS + r] = h_pred[(r0 + r) * HID + cc];
        hvF[cc * ROWS + r]  = h_prev[(r0 + r) * HID + cc];
    }
    __syncthreads();

    u64 acc[4];
    float* pDst = pA + s * 1024 + c * ROWS;

#define GEMM_ZERO() { acc[0] = acc[1] = acc[2] = acc[3] = 0ULL; }
#define REDUCE8(x) float x = ((pA[p] + pA[1024 + p]) + (pA[2048 + p] + pA[3072 + p])) \
                           + ((pA[4096 + p] + pA[5120 + p]) + (pA[6144 + p] + pA[7168 + p]))
#define REDUCE_LO(x) float x = (pA[p] + pA[1024 + p]) + (pA[2048 + p] + pA[3072 + p])
#define REDUCE_HI(x) float x = (pA[4096 + p] + pA[5120 + p]) + (pA[6144 + p] + pA[7168 + p])

    float outv, hcv;

    // ---- S1: v = h_pred @ Wv + bv -> bufC ----
    GEMM_ZERO();
    gemm_slice<KS>(Wv, bufA, c, k0, acc);
    part_store(pDst, acc);
    __syncthreads();
    { REDUCE8(v); bufC[p] = v + bv_r; }
    __syncthreads();

    // ---- S3: g1 = silu(h_pred@gW1_top + h_prev@gW1_bot + gb1) -> g1F ----
    GEMM_ZERO();
    gemm_slice<KS>(gW1, bufA, c, k0, acc);
    gemm_slice<KS>(gW1 + HID * HID, hvF, c, k0, acc);
    part_store(pDst, acc);
    __syncthreads();
    { REDUCE8(x); x += gb1_r; g1F[p] = x / (1.0f + __expf(-x)); }
    __syncthreads();

    // ---- S2+S4 merged: slices 0-3 do v@Wo (KS=32), slices 4-7 do g1@gW2 ----
    GEMM_ZERO();
    if (s < 4) {
        gemm_slice<2 * KS>(Wo, bufC, c, s * 2 * KS, acc);
    } else {
        gemm_slice<2 * KS>(gW2, g1F, c, (s - 4) * 2 * KS, acc);
    }
    part_store(pDst, acc);
    __syncthreads();
    {
        REDUCE_LO(v);                    // S2 partials (slices 0-3)
        outv = (float)NNODES * v + bo_r;
        REDUCE_HI(x);                    // S4 partials (slices 4-7)
        x += gb2_r;
        float g = 1.0f / (1.0f + __expf(-x));
        hcv = hvF[p] + g * outv;
        bufA[p] = hcv;                   // h_corr (h_pred dead)
    }
    __syncthreads();

    // ---- S5: m1 = relu(h_corr@mW1_top + h_prev@mW1_bot + mb1) -> bufC ----
    GEMM_ZERO();
    gemm_slice<KS>(mW1, bufA, c, k0, acc);
    gemm_slice<KS>(mW1 + HID * HID, hvF, c, k0, acc);
    part_store(pDst, acc);
    __syncthreads();
    { REDUCE8(x); bufC[p] = fmaxf(x + mb1_r, 0.0f); }
    __syncthreads();

    // ---- S6: mixed = h_corr + m1 @ mW2 + mb2 -> global ----
    GEMM_ZERO();
    gemm_slice<KS>(mW2, bufC, c, k0, acc);
    part_store(pDst, acc);
    __syncthreads();
    {
        REDUCE8(v);
        out[(r0 + (p & 7)) * HID + q] = hcv + v + mb2_r;
    }
}

extern "C" void kernel_launch(void* const* d_in, const int* in_sizes, int n_in,
                              void* d_out, int out_size) {
    // metadata order: h_prev, h_pred, adj_rows, adj_cols, Wq, bq, Wk, bk,
    //                 Wv, bv, Wo, bo, gW1, gb1, gW2, gb2, mW1, mb1, mW2, mb2
    const float* h_prev = (const float*)d_in[0];
    const float* h_pred = (const float*)d_in[1];
    // d_in[2..7] (adjacency, Wq/bq/Wk/bk) are algebraically dead.
    const float* Wv  = (const float*)d_in[8];
    const float* bv  = (const float*)d_in[9];
    const float* Wo  = (const float*)d_in[10];
    const float* bo  = (const float*)d_in[11];
    const float* gW1 = (const float*)d_in[12];
    const float* gb1 = (const float*)d_in[13];
    const float* gW2 = (const float*)d_in[14];
    const float* gb2 = (const float*)d_in[15];
    const float* mW1 = (const float*)d_in[16];
    const float* mb1 = (const float*)d_in[17];
    const float* mW2 = (const float*)d_in[18];
    const float* mb2 = (const float*)d_in[19];
    float* out = (float*)d_out;

    temporal_attn_fused<<<NNODES / ROWS, NTHREADS>>>(
        h_prev, h_pred, Wv, bv, Wo, bo,
        gW1, gb1, gW2, gb2, mW1, mb1, mW2, mb2, out);
}

// round 7
// speedup vs baseline: 1.4377x; 1.4361x over previous
#include <cuda_runtime.h>
#include <cuda_bf16.h>
#include <math.h>

// Attention path collapses (softmax rows sum to 1; T,S fully contracted):
//   y = 1024 * (h_pred @ Wv + bv)
// Only Wv/Wo projection + gate MLP + mixer MLP survive.
//
// R6: back to the 512-thread / 4-slice skeleton (best wall: R1 19.2us).
// Adds: cross-barrier weight prefetch (next stage's first 16-weight chunk
// LDG'd before the preceding __syncthreads), LDS.128 activation loads,
// warp-uniform S2+S4 merge, hoisted biases. 32KB static smem.

#define HID 128
#define ROWS 8
#define SLICES 4
#define KS 32                    // k-values per slice
#define NNODES 1024
#define NTHREADS 512

typedef unsigned long long u64;

__device__ __forceinline__ u64 fma2(u64 a, u64 b, u64 c) {
    u64 d;
    asm("fma.rn.f32x2 %0, %1, %2, %3;" : "=l"(d) : "l"(a), "l"(b), "l"(c));
    return d;
}

__device__ __forceinline__ void load16(const float* __restrict__ W, int c,
                                       int k, float w[16]) {
#pragma unroll
    for (int i = 0; i < 16; i++) w[i] = W[(k + i) * HID + c];
}

// 16 k-steps of the partial GEMM: activations via LDS.128 ([k][8 rows] fp32,
// warp-broadcast), weights already in registers.
__device__ __forceinline__ void fma16(const float* __restrict__ act, int k,
                                      const float w[16], u64 acc[4]) {
#pragma unroll
    for (int i = 0; i < 16; i++) {
        u64 ww;
        asm("mov.b64 %0, {%1, %1};" : "=l"(ww) : "f"(w[i]));
        const ulonglong2* a = (const ulonglong2*)(act + (k + i) * ROWS);
        ulonglong2 a01 = a[0];   // rows 0..3
        ulonglong2 a23 = a[1];   // rows 4..7
        acc[0] = fma2(a01.x, ww, acc[0]);
        acc[1] = fma2(a01.y, ww, acc[1]);
        acc[2] = fma2(a23.x, ww, acc[2]);
        acc[3] = fma2(a23.y, ww, acc[3]);
    }
}

__device__ __forceinline__ void part_store(float* dst, const u64 acc[4]) {
    ulonglong2* d = (ulonglong2*)dst;
    d[0] = make_ulonglong2(acc[0], acc[1]);
    d[1] = make_ulonglong2(acc[2], acc[3]);
}

extern "C" __global__ void __launch_bounds__(NTHREADS)
temporal_attn_fused(const float* __restrict__ h_prev,
                    const float* __restrict__ h_pred,
                    const float* __restrict__ Wv, const float* __restrict__ bv,
                    const float* __restrict__ Wo, const float* __restrict__ bo,
                    const float* __restrict__ gW1, const float* __restrict__ gb1,
                    const float* __restrict__ gW2, const float* __restrict__ gb2,
                    const float* __restrict__ mW1, const float* __restrict__ mb1,
                    const float* __restrict__ mW2, const float* __restrict__ mb2,
                    float* __restrict__ out) {
    __shared__ float bufA[HID * ROWS];         // 4KB  h_pred, later h_corr
    __shared__ float hvF[HID * ROWS];          // 4KB  h_prev
    __shared__ float bufC[HID * ROWS];         // 4KB  v, later m1
    __shared__ float g1F[HID * ROWS];          // 4KB  gate hidden
    __shared__ float pA[SLICES * HID * ROWS];  // 16KB partials

    const int tid = threadIdx.x;
    const int c = tid & (HID - 1);   // output column (GEMM phase)
    const int s = tid >> 7;          // k-slice 0..3 (warp-uniform)
    const int k0 = s * KS;
    const int r0 = blockIdx.x * ROWS;
    const int p0 = tid, p1 = tid + NTHREADS;   // elements owned in reduces
    const int q0 = p0 >> 3, q1 = p1 >> 3;      // their column indices

    // Hoisted bias loads (off the post-barrier critical paths).
    const float bv0 = bv[q0], bv1 = bv[q1];
    const float bo0 = bo[q0], bo1 = bo[q1];
    const float gb10 = gb1[q0], gb11 = gb1[q1];
    const float gb20 = gb2[q0], gb21 = gb2[q1];
    const float mb10 = mb1[q0], mb11 = mb1[q1];
    const float mb20 = mb2[q0], mb21 = mb2[q1];

    float wpre[16], wt[16];
    load16(Wv, c, k0, wpre);         // S1 chunk0, in flight during staging

    // Stage input tiles transposed: [k][r], coalesced global reads.
#pragma unroll
    for (int j = 0; j < 2; j++) {
        int g = tid + j * NTHREADS;
        int r = g >> 7, cc = g & (HID - 1);
        bufA[cc * ROWS + r] = h_pred[(r0 + r) * HID + cc];
        hvF[cc * ROWS + r]  = h_prev[(r0 + r) * HID + cc];
    }
    __syncthreads();

    u64 acc[4];
    float* pDst = pA + s * 1024 + c * ROWS;

#define GEMM_ZERO() { acc[0] = acc[1] = acc[2] = acc[3] = 0ULL; }
#define RED4(x, p)  float x = (pA[p] + pA[1024 + (p)]) + (pA[2048 + (p)] + pA[3072 + (p)])

    float outv0, outv1, hcv0, hcv1;
    const float* Wm = (s < 2) ? Wo : gW2;      // merged-stage matrix
    const int k0m = (s & 1) * 64;              // merged-stage k-offset

    // ---- S1: v = h_pred @ Wv + bv -> bufC ----
    GEMM_ZERO();
    fma16(bufA, k0, wpre, acc);
    load16(Wv, c, k0 + 16, wt);  fma16(bufA, k0 + 16, wt, acc);
    load16(gW1, c, k0, wpre);                  // prefetch S3 chunk0
    part_store(pDst, acc);
    __syncthreads();
    { RED4(v0, p0); bufC[p0] = v0 + bv0; RED4(v1, p1); bufC[p1] = v1 + bv1; }
    __syncthreads();

    // ---- S3: g1 = silu(h_pred@gW1_top + h_prev@gW1_bot + gb1) -> g1F ----
    GEMM_ZERO();
    fma16(bufA, k0, wpre, acc);
    load16(gW1, c, k0 + 16, wt);  fma16(bufA, k0 + 16, wt, acc);
    load16(gW1 + HID * HID, c, k0, wt);       fma16(hvF, k0, wt, acc);
    load16(gW1 + HID * HID, c, k0 + 16, wt);  fma16(hvF, k0 + 16, wt, acc);
    load16(Wm, c, k0m, wpre);                  // prefetch merged-stage chunk0
    part_store(pDst, acc);
    __syncthreads();
    {
        RED4(x0, p0); x0 += gb10; g1F[p0] = x0 / (1.0f + __expf(-x0));
        RED4(x1, p1); x1 += gb11; g1F[p1] = x1 / (1.0f + __expf(-x1));
    }
    __syncthreads();

    // ---- S2+S4 merged: slices 0-1 do v@Wo, slices 2-3 do g1@gW2 (KS=64) ----
    {
        const float* actm = (s < 2) ? bufC : g1F;
        GEMM_ZERO();
        fma16(actm, k0m, wpre, acc);
        load16(Wm, c, k0m + 16, wt);  fma16(actm, k0m + 16, wt, acc);
        load16(Wm, c, k0m + 32, wt);  fma16(actm, k0m + 32, wt, acc);
        load16(Wm, c, k0m + 48, wt);  fma16(actm, k0m + 48, wt, acc);
        load16(mW1, c, k0, wpre);              // prefetch S5 chunk0
        part_store(pDst, acc);
    }
    __syncthreads();
    {
        float v0 = pA[p0] + pA[1024 + p0];           // S2 partials (slices 0-1)
        float v1 = pA[p1] + pA[1024 + p1];
        outv0 = (float)NNODES * v0 + bo0;
        outv1 = (float)NNODES * v1 + bo1;
        float x0 = pA[2048 + p0] + pA[3072 + p0];    // S4 partials (slices 2-3)
        float x1 = pA[2048 + p1] + pA[3072 + p1];
        x0 += gb20; x1 += gb21;
        float g0 = 1.0f / (1.0f + __expf(-x0));
        float g1 = 1.0f / (1.0f + __expf(-x1));
        hcv0 = hvF[p0] + g0 * outv0;
        hcv1 = hvF[p1] + g1 * outv1;
        bufA[p0] = hcv0;                             // h_corr (h_pred dead)
        bufA[p1] = hcv1;
    }
    __syncthreads();

    // ---- S5: m1 = relu(h_corr@mW1_top + h_prev@mW1_bot + mb1) -> bufC ----
    GEMM_ZERO();
    fma16(bufA, k0, wpre, acc);
    load16(mW1, c, k0 + 16, wt);  fma16(bufA, k0 + 16, wt, acc);
    load16(mW1 + HID * HID, c, k0, wt);       fma16(hvF, k0, wt, acc);
    load16(mW1 + HID * HID, c, k0 + 16, wt);  fma16(hvF, k0 + 16, wt, acc);
    load16(mW2, c, k0, wpre);                  // prefetch S6 chunk0
    part_store(pDst, acc);
    __syncthreads();
    {
        RED4(x0, p0); bufC[p0] = fmaxf(x0 + mb10, 0.0f);
        RED4(x1, p1); bufC[p1] = fmaxf(x1 + mb11, 0.0f);
    }
    __syncthreads();

    // ---- S6: mixed = h_corr + m1 @ mW2 + mb2 -> global ----
    GEMM_ZERO();
    fma16(bufC, k0, wpre, acc);
    load16(mW2, c, k0 + 16, wt);  fma16(bufC, k0 + 16, wt, acc);
    part_store(pDst, acc);
    __syncthreads();
    {
        RED4(v0, p0);
        out[(r0 + (p0 & 7)) * HID + q0] = hcv0 + v0 + mb20;
        RED4(v1, p1);
        out[(r0 + (p1 & 7)) * HID + q1] = hcv1 + v1 + mb21;
    }
}

extern "C" void kernel_launch(void* const* d_in, const int* in_sizes, int n_in,
                              void* d_out, int out_size) {
    // metadata order: h_prev, h_pred, adj_rows, adj_cols, Wq, bq, Wk, bk,
    //                 Wv, bv, Wo, bo, gW1, gb1, gW2, gb2, mW1, mb1, mW2, mb2
    const float* h_prev = (const float*)d_in[0];
    const float* h_pred = (const float*)d_in[1];
    // d_in[2..7] (adjacency, Wq/bq/Wk/bk) are algebraically dead.
    const float* Wv  = (const float*)d_in[8];
    const float* bv  = (const float*)d_in[9];
    const float* Wo  = (const float*)d_in[10];
    const float* bo  = (const float*)d_in[11];
    const float* gW1 = (const float*)d_in[12];
    const float* gb1 = (const float*)d_in[13];
    const float* gW2 = (const float*)d_in[14];
    const float* gb2 = (const float*)d_in[15];
    const float* mW1 = (const float*)d_in[16];
    const float* mb1 = (const float*)d_in[17];
    const float* mW2 = (const float*)d_in[18];
    const float* mb2 = (const float*)d_in[19];
    float* out = (float*)d_out;

    temporal_attn_fused<<<NNODES / ROWS, NTHREADS>>>(
        h_prev, h_pred, Wv, bv, Wo, bo,
        gW1, gb1, gW2, gb2, mW1, mb1, mW2, mb2, out);
}

// round 8
// speedup vs baseline: 1.5435x; 1.0736x over previous
#include <cuda_runtime.h>
#include <cuda_bf16.h>
#include <math.h>

// Attention path collapses (softmax rows sum to 1; T,S fully contracted):
//   y = 1024 * (h_pred @ Wv + bv)
// Only Wv/Wo projection + gate MLP + mixer MLP survive.
//
// R7: R6 + __launch_bounds__(512, 1). R6's bare __launch_bounds__(512) let
// ptxas cap at 64 regs, spilling the 32-reg weight-prefetch arrays to local
// memory (defeating the prefetch and inflating L1 traffic). minBlocks=1
// raises the budget to 128 regs; prefetch stays in registers.

#define HID 128
#define ROWS 8
#define SLICES 4
#define KS 32                    // k-values per slice
#define NNODES 1024
#define NTHREADS 512

typedef unsigned long long u64;

__device__ __forceinline__ u64 fma2(u64 a, u64 b, u64 c) {
    u64 d;
    asm("fma.rn.f32x2 %0, %1, %2, %3;" : "=l"(d) : "l"(a), "l"(b), "l"(c));
    return d;
}

__device__ __forceinline__ void load16(const float* __restrict__ W, int c,
                                       int k, float w[16]) {
#pragma unroll
    for (int i = 0; i < 16; i++) w[i] = W[(k + i) * HID + c];
}

// 16 k-steps of the partial GEMM: activations via LDS.128 ([k][8 rows] fp32,
// warp-broadcast), weights already in registers.
__device__ __forceinline__ void fma16(const float* __restrict__ act, int k,
                                      const float w[16], u64 acc[4]) {
#pragma unroll
    for (int i = 0; i < 16; i++) {
        u64 ww;
        asm("mov.b64 %0, {%1, %1};" : "=l"(ww) : "f"(w[i]));
        const ulonglong2* a = (const ulonglong2*)(act + (k + i) * ROWS);
        ulonglong2 a01 = a[0];   // rows 0..3
        ulonglong2 a23 = a[1];   // rows 4..7
        acc[0] = fma2(a01.x, ww, acc[0]);
        acc[1] = fma2(a01.y, ww, acc[1]);
        acc[2] = fma2(a23.x, ww, acc[2]);
        acc[3] = fma2(a23.y, ww, acc[3]);
    }
}

__device__ __forceinline__ void part_store(float* dst, const u64 acc[4]) {
    ulonglong2* d = (ulonglong2*)dst;
    d[0] = make_ulonglong2(acc[0], acc[1]);
    d[1] = make_ulonglong2(acc[2], acc[3]);
}

extern "C" __global__ void __launch_bounds__(NTHREADS, 1)
temporal_attn_fused(const float* __restrict__ h_prev,
                    const float* __restrict__ h_pred,
                    const float* __restrict__ Wv, const float* __restrict__ bv,
                    const float* __restrict__ Wo, const float* __restrict__ bo,
                    const float* __restrict__ gW1, const float* __restrict__ gb1,
                    const float* __restrict__ gW2, const float* __restrict__ gb2,
                    const float* __restrict__ mW1, const float* __restrict__ mb1,
                    const float* __restrict__ mW2, const float* __restrict__ mb2,
                    float* __restrict__ out) {
    __shared__ float bufA[HID * ROWS];         // 4KB  h_pred, later h_corr
    __shared__ float hvF[HID * ROWS];          // 4KB  h_prev
    __shared__ float bufC[HID * ROWS];         // 4KB  v, later m1
    __shared__ float g1F[HID * ROWS];          // 4KB  gate hidden
    __shared__ float pA[SLICES * HID * ROWS];  // 16KB partials

    const int tid = threadIdx.x;
    const int c = tid & (HID - 1);   // output column (GEMM phase)
    const int s = tid >> 7;          // k-slice 0..3 (warp-uniform)
    const int k0 = s * KS;
    const int r0 = blockIdx.x * ROWS;
    const int p0 = tid, p1 = tid + NTHREADS;   // elements owned in reduces
    const int q0 = p0 >> 3, q1 = p1 >> 3;      // their column indices

    // Hoisted bias loads (off the post-barrier critical paths).
    const float bv0 = bv[q0], bv1 = bv[q1];
    const float bo0 = bo[q0], bo1 = bo[q1];
    const float gb10 = gb1[q0], gb11 = gb1[q1];
    const float gb20 = gb2[q0], gb21 = gb2[q1];
    const float mb10 = mb1[q0], mb11 = mb1[q1];
    const float mb20 = mb2[q0], mb21 = mb2[q1];

    float wpre[16], wt[16];
    load16(Wv, c, k0, wpre);         // S1 chunk0, in flight during staging

    // Stage input tiles transposed: [k][r], coalesced global reads.
#pragma unroll
    for (int j = 0; j < 2; j++) {
        int g = tid + j * NTHREADS;
        int r = g >> 7, cc = g & (HID - 1);
        bufA[cc * ROWS + r] = h_pred[(r0 + r) * HID + cc];
        hvF[cc * ROWS + r]  = h_prev[(r0 + r) * HID + cc];
    }
    __syncthreads();

    u64 acc[4];
    float* pDst = pA + s * 1024 + c * ROWS;

#define GEMM_ZERO() { acc[0] = acc[1] = acc[2] = acc[3] = 0ULL; }
#define RED4(x, p)  float x = (pA[p] + pA[1024 + (p)]) + (pA[2048 + (p)] + pA[3072 + (p)])

    float outv0, outv1, hcv0, hcv1;
    const float* Wm = (s < 2) ? Wo : gW2;      // merged-stage matrix
    const int k0m = (s & 1) * 64;              // merged-stage k-offset

    // ---- S1: v = h_pred @ Wv + bv -> bufC ----
    GEMM_ZERO();
    fma16(bufA, k0, wpre, acc);
    load16(Wv, c, k0 + 16, wt);  fma16(bufA, k0 + 16, wt, acc);
    load16(gW1, c, k0, wpre);                  // prefetch S3 chunk0
    part_store(pDst, acc);
    __syncthreads();
    { RED4(v0, p0); bufC[p0] = v0 + bv0; RED4(v1, p1); bufC[p1] = v1 + bv1; }
    __syncthreads();

    // ---- S3: g1 = silu(h_pred@gW1_top + h_prev@gW1_bot + gb1) -> g1F ----
    GEMM_ZERO();
    fma16(bufA, k0, wpre, acc);
    load16(gW1, c, k0 + 16, wt);  fma16(bufA, k0 + 16, wt, acc);
    load16(gW1 + HID * HID, c, k0, wt);       fma16(hvF, k0, wt, acc);
    load16(gW1 + HID * HID, c, k0 + 16, wt);  fma16(hvF, k0 + 16, wt, acc);
    load16(Wm, c, k0m, wpre);                  // prefetch merged-stage chunk0
    part_store(pDst, acc);
    __syncthreads();
    {
        RED4(x0, p0); x0 += gb10; g1F[p0] = x0 / (1.0f + __expf(-x0));
        RED4(x1, p1); x1 += gb11; g1F[p1] = x1 / (1.0f + __expf(-x1));
    }
    __syncthreads();

    // ---- S2+S4 merged: slices 0-1 do v@Wo, slices 2-3 do g1@gW2 (KS=64) ----
    {
        const float* actm = (s < 2) ? bufC : g1F;
        GEMM_ZERO();
        fma16(actm, k0m, wpre, acc);
        load16(Wm, c, k0m + 16, wt);  fma16(actm, k0m + 16, wt, acc);
        load16(Wm, c, k0m + 32, wt);  fma16(actm, k0m + 32, wt, acc);
        load16(Wm, c, k0m + 48, wt);  fma16(actm, k0m + 48, wt, acc);
        load16(mW1, c, k0, wpre);              // prefetch S5 chunk0
        part_store(pDst, acc);
    }
    __syncthreads();
    {
        float v0 = pA[p0] + pA[1024 + p0];           // S2 partials (slices 0-1)
        float v1 = pA[p1] + pA[1024 + p1];
        outv0 = (float)NNODES * v0 + bo0;
        outv1 = (float)NNODES * v1 + bo1;
        float x0 = pA[2048 + p0] + pA[3072 + p0];    // S4 partials (slices 2-3)
        float x1 = pA[2048 + p1] + pA[3072 + p1];
        x0 += gb20; x1 += gb21;
        float g0 = 1.0f / (1.0f + __expf(-x0));
        float g1 = 1.0f / (1.0f + __expf(-x1));
        hcv0 = hvF[p0] + g0 * outv0;
        hcv1 = hvF[p1] + g1 * outv1;
        bufA[p0] = hcv0;                             // h_corr (h_pred dead)
        bufA[p1] = hcv1;
    }
    __syncthreads();

    // ---- S5: m1 = relu(h_corr@mW1_top + h_prev@mW1_bot + mb1) -> bufC ----
    GEMM_ZERO();
    fma16(bufA, k0, wpre, acc);
    load16(mW1, c, k0 + 16, wt);  fma16(bufA, k0 + 16, wt, acc);
    load16(mW1 + HID * HID, c, k0, wt);       fma16(hvF, k0, wt, acc);
    load16(mW1 + HID * HID, c, k0 + 16, wt);  fma16(hvF, k0 + 16, wt, acc);
    load16(mW2, c, k0, wpre);                  // prefetch S6 chunk0
    part_store(pDst, acc);
    __syncthreads();
    {
        RED4(x0, p0); bufC[p0] = fmaxf(x0 + mb10, 0.0f);
        RED4(x1, p1); bufC[p1] = fmaxf(x1 + mb11, 0.0f);
    }
    __syncthreads();

    // ---- S6: mixed = h_corr + m1 @ mW2 + mb2 -> global ----
    GEMM_ZERO();
    fma16(bufC, k0, wpre, acc);
    load16(mW2, c, k0 + 16, wt);  fma16(bufC, k0 + 16, wt, acc);
    part_store(pDst, acc);
    __syncthreads();
    {
        RED4(v0, p0);
        out[(r0 + (p0 & 7)) * HID + q0] = hcv0 + v0 + mb20;
        RED4(v1, p1);
        out[(r0 + (p1 & 7)) * HID + q1] = hcv1 + v1 + mb21;
    }
}

extern "C" void kernel_launch(void* const* d_in, const int* in_sizes, int n_in,
                              void* d_out, int out_size) {
    // metadata order: h_prev, h_pred, adj_rows, adj_cols, Wq, bq, Wk, bk,
    //                 Wv, bv, Wo, bo, gW1, gb1, gW2, gb2, mW1, mb1, mW2, mb2
    const float* h_prev = (const float*)d_in[0];
    const float* h_pred = (const float*)d_in[1];
    // d_in[2..7] (adjacency, Wq/bq/Wk/bk) are algebraically dead.
    const float* Wv  = (const float*)d_in[8];
    const float* bv  = (const float*)d_in[9];
    const float* Wo  = (const float*)d_in[10];
    const float* bo  = (const float*)d_in[11];
    const float* gW1 = (const float*)d_in[12];
    const float* gb1 = (const float*)d_in[13];
    const float* gW2 = (const float*)d_in[14];
    const float* gb2 = (const float*)d_in[15];
    const float* mW1 = (const float*)d_in[16];
    const float* mb1 = (const float*)d_in[17];
    const float* mW2 = (const float*)d_in[18];
    const float* mb2 = (const float*)d_in[19];
    float* out = (float*)d_out;

    temporal_attn_fused<<<NNODES / ROWS, NTHREADS>>>(
        h_prev, h_pred, Wv, bv, Wo, bo,
        gW1, gb1, gW2, gb2, mW1, mb1, mW2, mb2, out);
}